// round 12
// baseline (speedup 1.0000x reference)
#include <cuda_runtime.h>
#include <math.h>

// ---------------- fixed CT geometry ----------------
#define IMG   512
#define NDET  768
#define NV    360
#define GLEN  (2*NDET-1)

#define PIXd  0.7433
#define DSOd  595.0
#define DSDd  1085.6              // 595.0 + 490.6
#define DETd  1.2858
#define DGd   (DETd / DSDd)       // equiangular pitch (rad/bin)
#define INVDGd (DSDd / DETd)
#define SCALEd (DGd * 2.0 * M_PI / 360.0)   // fold q*=DGAMMA and *=2pi/NV

// padded q row: [16 zero | 768 data | 16 zero]; i0 in [-13,779] stays in-row
#define QPAD    16
#define QSTRIDE 800

typedef unsigned long long u64;

// ---- packed f32x2 helpers (sm_103a FFMA2) ----
__device__ __forceinline__ u64 pk2(float a, float b) {
    u64 r; asm("mov.b64 %0, {%1, %2};" : "=l"(r) : "f"(a), "f"(b)); return r;
}
__device__ __forceinline__ void upk2(u64 v, float& a, float& b) {
    asm("mov.b64 {%0, %1}, %2;" : "=f"(a), "=f"(b) : "l"(v));
}
__device__ __forceinline__ u64 ffma2(u64 a, u64 b, u64 c) {
    u64 d; asm("fma.rn.f32x2 %0, %1, %2, %3;" : "=l"(d) : "l"(a), "l"(b), "l"(c));
    return d;
}

// ---------------- device scratch (no allocations allowed) ----------------
__device__ float2 cs_tab[NV];               // (cos beta, sin beta)
__device__ float2 q_part[2][NV * NDET];     // split-K partial conv results
__device__ float4 q_pack[NV * QSTRIDE];     // (q0, q1, dq0, dq1), zero-padded
__device__ float  part_img[3][2 * IMG * IMG]; // rot-90/180/270 contributions

// ---------------- conv split-K: block = (view, k-half) ---------------------
// Block h handles taps k in [384h, 384h+384) for all 768 outputs (2/thread).
// Ramp taps stored duplicated (g,g) so LDS.64 yields a packed FFMA2 operand.
// Local tap index for output o, local tap kk is o - kk + 383 in BOTH halves.
__global__ void __launch_bounds__(384) conv_kernel(const float* __restrict__ proj) {
    __shared__ float2 p2[384];               // this half's cosine-weighted bins
    __shared__ float2 gs2[1151];             // (g, g) duplicated ramp taps

    const int v   = blockIdx.x >> 1;
    const int h   = blockIdx.x & 1;
    const int tid = threadIdx.x;
    const int kbase = h * 384;
    const int idx0  = h ? 0 : 384;           // global g-index of gs2[0]

    if (h == 0 && tid == 0) {                // per-view angle (double-accurate)
        double sb, cb;
        sincospi((double)v / 180.0, &sb, &cb);
        cs_tab[v] = make_float2((float)cb, (float)sb);
    }
    for (int i = tid; i < 1151; i += 384) {  // ramp taps (fp32: 2e-7 rel)
        int n = (i + idx0) - (NDET - 1);
        float g;
        if (n == 0) {
            g = (float)(SCALEd / (8.0 * DGd * DGd));
        } else if (n & 1) {
            float s = sinf((float)n * (float)DGd) * (float)M_PI;
            g = (float)(-0.5 * SCALEd) / (s * s);
        } else {
            g = 0.0f;
        }
        gs2[i] = make_float2(g, g);
    }
    {   // cosine-weighted projections for this half's bins
        int bin = kbase + tid;
        float gam = ((float)bin - 383.5f) * (float)DGd;
        float cw  = 595.0f * cosf(gam);
        p2[tid] = make_float2(proj[(0 * NV + v) * NDET + bin] * cw,
                              proj[(1 * NV + v) * NDET + bin] * cw);
    }
    __syncthreads();

    const int t  = tid;                      // output bins t and t+384
    const int t2 = tid + 384;
    const float g0 = (float)(SCALEd / (8.0 * DGd * DGd));

    // center tap (output == k) belongs to the half containing that output
    float a0 = 0.f, a1 = 0.f, b0 = 0.f, b1 = 0.f;
    if (h == 0) { float2 pc = p2[t];         a0 = pc.x * g0; a1 = pc.y * g0; }
    else        { float2 pc = p2[t2 - 384];  b0 = pc.x * g0; b1 = pc.y * g0; }
    u64 accA = pk2(a0, a1);
    u64 accB = pk2(b0, b1);

    const u64* p2u  = (const u64*)p2;
    const u64* gsu  = (const u64*)gs2;
    const int k0 = (t + 1) & 1;              // parity making (output - k) odd
#pragma unroll 8
    for (int kk = k0; kk < 384; kk += 2) {
        u64 pv = p2u[kk];                    // broadcast LDS.64
        accA = ffma2(pv, gsu[t  - kk + 383], accA);
        accB = ffma2(pv, gsu[t2 - kk + 383], accB);
    }
    upk2(accA, a0, a1);
    upk2(accB, b0, b1);
    q_part[h][v * NDET + t]  = make_float2(a0, a1);
    q_part[h][v * NDET + t2] = make_float2(b0, b1);
}

// ---------------- pack: sum halves + pre-diff + interleave + pads ----------
// Output order (q0, q1, dq0, dq1): two aligned f32x2 lanes for bp's FFMA2.
__global__ void __launch_bounds__(NDET) pack_kernel() {
    __shared__ float2 qs[NDET];
    const int v = blockIdx.x;
    const int t = threadIdx.x;

    float2 qa0 = q_part[0][v * NDET + t];
    float2 qa1 = q_part[1][v * NDET + t];
    qs[t] = make_float2(qa0.x + qa1.x, qa0.y + qa1.y);   // fixed order: determ.
    if (t < QPAD) {
        q_pack[v * QSTRIDE + t]               = make_float4(0.f, 0.f, 0.f, 0.f);
        q_pack[v * QSTRIDE + QPAD + NDET + t] = make_float4(0.f, 0.f, 0.f, 0.f);
    }
    __syncthreads();

    float2 qa = qs[t];
    float2 qb = qs[min(t + 1, NDET - 1)];
    q_pack[v * QSTRIDE + QPAD + t] =
        make_float4(qa.x, qa.y, qb.x - qa.x, qb.y - qa.y);
}

// ---------------- backprojection with 4-fold rotation symmetry -------------
// One geometry+asin serves 4 pixel-view updates; accumulation in FFMA2 pairs.
__global__ void __launch_bounds__(128, 12) bp_kernel(float* __restrict__ out) {
    __shared__ float2 cs_s[NV / 4];
    const int tid = threadIdx.y * 16 + threadIdx.x;
    if (tid < NV / 4) cs_s[tid] = cs_tab[tid];
    __syncthreads();

    const int j = (blockIdx.x << 4) + threadIdx.x;
    const int i = (blockIdx.y << 3) + threadIdx.y;

    const float x = ((float)j - 255.5f) * (float)PIXd;
    const float y = ((float)i - 255.5f) * (float)PIXd;
    const float DSOf = 595.0f;

    // asin Taylor coefficients * (1/DGAMMA), degree 13 (tail 9.4e-8 rad)
    const float A0 = (float)(INVDGd);
    const float A1 = (float)(INVDGd / 6.0);
    const float A2 = (float)(INVDGd * 0.075);
    const float A3 = (float)(INVDGd * 0.044642857);
    const float A4 = (float)(INVDGd * 0.030381944);
    const float A5 = (float)(INVDGd * 0.022372159);
    const float A6 = (float)(INVDGd * 0.017352764);

    u64 accS  = 0ULL;                        // (b0, b1) self,    views 0..89
    u64 acc90 = 0ULL;                        // rot +90 pixel,    views 90..179
    u64 acc180 = 0ULL;                       // rot 180 pixel,    views 180..269
    u64 acc270 = 0ULL;                       // rot 270 pixel,    views 270..359

    const float4* __restrict__ qp = q_pack + QPAD;

#pragma unroll 3
    for (int v = 0; v < NV / 4; ++v) {
        float2 cs = cs_s[v];
        float u  = fmaf(cs.x, x,  cs.y * y);
        float cr = fmaf(cs.y, x, -cs.x * y);
        float dt = DSOf - u;
        float L2 = fmaf(dt, dt, cr * cr);
        float rsq;
        asm("rsqrt.approx.f32 %0, %1;" : "=f"(rsq) : "f"(L2));
        float s  = cr * rsq;                 // sin(theta), dt > 0 always
        float s2 = s * s;
        float p  = fmaf(A6, s2, A5);
        p = fmaf(p, s2, A4);
        p = fmaf(p, s2, A3);
        p = fmaf(p, s2, A2);
        p = fmaf(p, s2, A1);
        p = fmaf(p, s2, A0);
        float tv = s * p;                    // g - 383.5 (detector offset)
        float g  = tv + 383.5f;

        float T  = (g - 0.5f) + 12582912.0f; // round(g-0.5) == floor(g)
        int   i0 = __float_as_int(T) - 0x4B400000;
        float fg = T - 12582912.0f;
        float w_ = g - fg;
        float m  = rsq * rsq;                // 1/L2
        float wl = (fabsf(tv) <= 383.5f) ? m : 0.0f;   // g in [0,767]
        u64 w2  = pk2(w_, w_);
        u64 wl2 = pk2(wl, wl);

        const ulonglong2* qv = (const ulonglong2*)(qp + v * QSTRIDE + i0);
        ulonglong2 qa = qv[0];                      // view v
        ulonglong2 qb = qv[ 90 * QSTRIDE];          // view v+90
        ulonglong2 qc = qv[180 * QSTRIDE];          // view v+180
        ulonglong2 qd = qv[270 * QSTRIDE];          // view v+270
        accS   = ffma2(ffma2(w2, qa.y, qa.x), wl2, accS);
        acc90  = ffma2(ffma2(w2, qb.y, qb.x), wl2, acc90);
        acc180 = ffma2(ffma2(w2, qc.y, qc.x), wl2, acc180);
        acc270 = ffma2(ffma2(w2, qd.y, qd.x), wl2, acc270);
    }

    float aS0, aS1, a90_0, a90_1, a180_0, a180_1, a270_0, a270_1;
    upk2(accS,   aS0,   aS1);
    upk2(acc90,  a90_0, a90_1);
    upk2(acc180, a180_0, a180_1);
    upk2(acc270, a270_0, a270_1);

    out[i * IMG + j]             = aS0;
    out[IMG * IMG + i * IMG + j] = aS1;
    // rot +90: pixel (i', j') = (j, 511-i)
    part_img[0][j * IMG + (IMG - 1 - i)]             = a90_0;
    part_img[0][IMG * IMG + j * IMG + (IMG - 1 - i)] = a90_1;
    // rot 180: (511-i, 511-j)
    part_img[1][(IMG - 1 - i) * IMG + (IMG - 1 - j)]             = a180_0;
    part_img[1][IMG * IMG + (IMG - 1 - i) * IMG + (IMG - 1 - j)] = a180_1;
    // rot 270: (511-j, i)
    part_img[2][(IMG - 1 - j) * IMG + i]             = a270_0;
    part_img[2][IMG * IMG + (IMG - 1 - j) * IMG + i] = a270_1;
}

// ---------------- combine: out += s90 + s180 + s270 ------------------------
__global__ void __launch_bounds__(512) combine_kernel(float* __restrict__ out) {
    int t = blockIdx.x * 512 + threadIdx.x;          // float4 index
    float4* o = (float4*)out;
    const float4* p0 = (const float4*)part_img[0];
    const float4* p1 = (const float4*)part_img[1];
    const float4* p2 = (const float4*)part_img[2];
    float4 a = o[t], b = p0[t], c = p1[t], d = p2[t];
    o[t] = make_float4(a.x + b.x + c.x + d.x,
                       a.y + b.y + c.y + d.y,
                       a.z + b.z + c.z + d.z,
                       a.w + b.w + c.w + d.w);
}

// ---------------- entry point ----------------
extern "C" void kernel_launch(void* const* d_in, const int* in_sizes, int n_in,
                              void* d_out, int out_size) {
    (void)in_sizes; (void)n_in; (void)out_size;
    const float* proj = (const float*)d_in[0];   // [2, 360, 768] f32
    float* out = (float*)d_out;                  // [2, 512, 512] f32

    conv_kernel<<<2 * NV, 384>>>(proj);
    pack_kernel<<<NV, NDET>>>();
    bp_kernel<<<dim3(IMG / 16, IMG / 8), dim3(16, 8)>>>(out);
    combine_kernel<<<(2 * IMG * IMG / 4) / 512, 512>>>(out);
}

// round 14
// speedup vs baseline: 1.1596x; 1.1596x over previous
#include <cuda_runtime.h>
#include <math.h>

// ---------------- fixed CT geometry ----------------
#define IMG   512
#define NDET  768
#define NV    360
#define GLEN  (2*NDET-1)

#define PIXd  0.7433
#define DSOd  595.0
#define DSDd  1085.6              // 595.0 + 490.6
#define DETd  1.2858
#define DGd   (DETd / DSDd)       // equiangular pitch (rad/bin)
#define INVDGd (DSDd / DETd)
#define SCALEd (DGd * 2.0 * M_PI / 360.0)   // fold q*=DGAMMA and *=2pi/NV

// padded q row: [16 zero | 768 data | 16 zero]; i0 in [-13,779] stays in-row
#define QPAD    16
#define QSTRIDE 800

// ---------------- device scratch (no allocations allowed) ----------------
__device__ float2 cs_tab[NV];               // (cos beta, sin beta)
__device__ float2 q_part[2][NV * NDET];     // split-K partial conv results
__device__ float4 q_pack[NV * QSTRIDE];     // (q0, dq0, q1, dq1), zero-padded

// ---------------- conv split-K (R11 proven form, unchanged) ----------------
__global__ void __launch_bounds__(384) conv_kernel(const float* __restrict__ proj) {
    __shared__ float2 p2[384];               // this half's cosine-weighted bins
    __shared__ float  gs[1151];              // this half's ramp taps

    const int v   = blockIdx.x >> 1;
    const int h   = blockIdx.x & 1;
    const int tid = threadIdx.x;
    const int kbase = h * 384;
    const int idx0  = h ? 0 : 384;           // global g-index of gs[0]

    if (h == 0 && tid == 0) {                // per-view angle (double-accurate)
        double sb, cb;
        sincospi((double)v / 180.0, &sb, &cb);
        cs_tab[v] = make_float2((float)cb, (float)sb);
    }
    for (int i = tid; i < 1151; i += 384) {  // ramp taps (fp32: 2e-7 rel)
        int n = (i + idx0) - (NDET - 1);
        float g;
        if (n == 0) {
            g = (float)(SCALEd / (8.0 * DGd * DGd));
        } else if (n & 1) {
            float s = sinf((float)n * (float)DGd) * (float)M_PI;
            g = (float)(-0.5 * SCALEd) / (s * s);
        } else {
            g = 0.0f;
        }
        gs[i] = g;
    }
    {   // cosine-weighted projections for this half's bins
        int bin = kbase + tid;
        float gam = ((float)bin - 383.5f) * (float)DGd;
        float cw  = 595.0f * cosf(gam);
        p2[tid] = make_float2(proj[(0 * NV + v) * NDET + bin] * cw,
                              proj[(1 * NV + v) * NDET + bin] * cw);
    }
    __syncthreads();

    const int t  = tid;                      // output bins t and t+384
    const int t2 = tid + 384;
    const float g0 = (float)(SCALEd / (8.0 * DGd * DGd));

    float a0 = 0.f, a1 = 0.f, b0 = 0.f, b1 = 0.f;
    if (h == 0) { float2 pc = p2[t];         a0 = pc.x * g0; a1 = pc.y * g0; }
    else        { float2 pc = p2[t2 - 384];  b0 = pc.x * g0; b1 = pc.y * g0; }

    const int k0 = (t + 1) & 1;              // parity making (output - k) odd
#pragma unroll 8
    for (int kk = k0; kk < 384; kk += 2) {
        float2 p  = p2[kk];                  // broadcast LDS.64
        float gva = gs[t  - kk + 383];
        float gvb = gs[t2 - kk + 383];
        a0 = fmaf(p.x, gva, a0);
        a1 = fmaf(p.y, gva, a1);
        b0 = fmaf(p.x, gvb, b0);
        b1 = fmaf(p.y, gvb, b1);
    }
    q_part[h][v * NDET + t]  = make_float2(a0, a1);
    q_part[h][v * NDET + t2] = make_float2(b0, b1);
}

// ---------------- pack: sum halves + pre-diff + interleave + pads ----------
__global__ void __launch_bounds__(NDET) pack_kernel() {
    __shared__ float2 qs[NDET];
    const int v = blockIdx.x;
    const int t = threadIdx.x;

    float2 qa0 = q_part[0][v * NDET + t];
    float2 qa1 = q_part[1][v * NDET + t];
    qs[t] = make_float2(qa0.x + qa1.x, qa0.y + qa1.y);   // fixed order: determ.
    if (t < QPAD) {
        q_pack[v * QSTRIDE + t]               = make_float4(0.f, 0.f, 0.f, 0.f);
        q_pack[v * QSTRIDE + QPAD + NDET + t] = make_float4(0.f, 0.f, 0.f, 0.f);
    }
    __syncthreads();

    float2 qa = qs[t];
    float2 qb = qs[min(t + 1, NDET - 1)];
    q_pack[v * QSTRIDE + QPAD + t] =
        make_float4(qa.x, qb.x - qa.x, qa.y, qb.y - qa.y);
}

// ---------------- orbit backprojection ------------------------------------
// Thread owns the full rotation orbit {P, rP, r2P, r3P} of one quadrant pixel.
// With u = cb*x+sb*y, cr = sb*x-cb*y for P, the rotated pixels' geometries are
// permutations: rP -> (cr, -u), r2P -> (-u, -cr), r3P -> (-cr, u).
// geom(r^k P, v) serves views v, v+90, v+180, v+270 for pixels r^k P, r^k+1 P...
// All 16 updates per view land in this thread's 8 accumulators: no scratch,
// no combine kernel.
struct Acc { float b0, b1; };

__device__ __forceinline__ void geom_update(
    float u, float cr, const float4* __restrict__ base,
    float A0, float A1, float A2, float A3, float A4, float A5, float A6,
    Acc& m0, Acc& m1, Acc& m2, Acc& m3)   // accumulators for v, v+90, v+180, v+270
{
    const float DSOf = 595.0f;
    float dt = DSOf - u;
    float L2 = fmaf(dt, dt, cr * cr);
    float rsq;
    asm("rsqrt.approx.f32 %0, %1;" : "=f"(rsq) : "f"(L2));
    float s  = cr * rsq;                     // sin(theta), dt > 0 always
    float s2 = s * s;
    float p  = fmaf(A6, s2, A5);
    p = fmaf(p, s2, A4);
    p = fmaf(p, s2, A3);
    p = fmaf(p, s2, A2);
    p = fmaf(p, s2, A1);
    p = fmaf(p, s2, A0);
    float tv = s * p;                        // g - 383.5
    float g  = tv + 383.5f;

    float T  = (g - 0.5f) + 12582912.0f;     // round(g-0.5) == floor(g)
    int   i0 = __float_as_int(T) - 0x4B400000;
    float fg = T - 12582912.0f;
    float w  = g - fg;
    float m  = rsq * rsq;                    // 1/L2
    float wl = (fabsf(tv) <= 383.5f) ? m : 0.0f;   // g in [0,767]

    const float4* qv = base + i0;
    float4 qa = qv[0];                       // view v
    float4 qb = qv[ 90 * QSTRIDE];           // view v+90
    float4 qc = qv[180 * QSTRIDE];           // view v+180
    float4 qd = qv[270 * QSTRIDE];           // view v+270
    m0.b0 = fmaf(fmaf(w, qa.y, qa.x), wl, m0.b0);
    m0.b1 = fmaf(fmaf(w, qa.w, qa.z), wl, m0.b1);
    m1.b0 = fmaf(fmaf(w, qb.y, qb.x), wl, m1.b0);
    m1.b1 = fmaf(fmaf(w, qb.w, qb.z), wl, m1.b1);
    m2.b0 = fmaf(fmaf(w, qc.y, qc.x), wl, m2.b0);
    m2.b1 = fmaf(fmaf(w, qc.w, qc.z), wl, m2.b1);
    m3.b0 = fmaf(fmaf(w, qd.y, qd.x), wl, m3.b0);
    m3.b1 = fmaf(fmaf(w, qd.w, qd.z), wl, m3.b1);
}

__global__ void __launch_bounds__(64) bp_kernel(float* __restrict__ out) {
    __shared__ float2 cs_s[NV / 4];
    const int tid = threadIdx.y * 16 + threadIdx.x;
    for (int s = tid; s < NV / 4; s += 64) cs_s[s] = cs_tab[s];  // FIXED: full load
    __syncthreads();

    const int j = (blockIdx.x << 4) + threadIdx.x;   // quadrant col 0..255
    const int i = (blockIdx.y << 2) + threadIdx.y;   // quadrant row 0..255

    const float x = ((float)j - 255.5f) * (float)PIXd;
    const float y = ((float)i - 255.5f) * (float)PIXd;

    // asin Taylor coefficients * (1/DGAMMA), degree 13
    const float A0 = (float)(INVDGd);
    const float A1 = (float)(INVDGd / 6.0);
    const float A2 = (float)(INVDGd * 0.075);
    const float A3 = (float)(INVDGd * 0.044642857);
    const float A4 = (float)(INVDGd * 0.030381944);
    const float A5 = (float)(INVDGd * 0.022372159);
    const float A6 = (float)(INVDGd * 0.017352764);

    Acc aP  = {0.f, 0.f};                    // pixel P      = (i, j)
    Acc aR  = {0.f, 0.f};                    // pixel rP     = (j, 511-i)
    Acc aR2 = {0.f, 0.f};                    // pixel r2P    = (511-i, 511-j)
    Acc aR3 = {0.f, 0.f};                    // pixel r3P    = (511-j, i)

    const float4* __restrict__ base0 = q_pack + QPAD;

#pragma unroll 2
    for (int v = 0; v < NV / 4; ++v) {
        float2 cs = cs_s[v];
        float u0  = fmaf(cs.x, x,  cs.y * y);
        float cr0 = fmaf(cs.y, x, -cs.x * y);
        const float4* base = base0 + v * QSTRIDE;

        // G(P):   serves P@v,   rP@v+90, r2P@v+180, r3P@v+270
        geom_update( u0,  cr0, base, A0,A1,A2,A3,A4,A5,A6, aP,  aR,  aR2, aR3);
        // G(rP):  serves rP@v, r2P@v+90, r3P@v+180, P@v+270
        geom_update( cr0, -u0, base, A0,A1,A2,A3,A4,A5,A6, aR,  aR2, aR3, aP );
        // G(r2P): serves r2P@v, r3P@v+90, P@v+180, rP@v+270
        geom_update(-u0, -cr0, base, A0,A1,A2,A3,A4,A5,A6, aR2, aR3, aP,  aR );
        // G(r3P): serves r3P@v, P@v+90, rP@v+180, r2P@v+270
        geom_update(-cr0,  u0, base, A0,A1,A2,A3,A4,A5,A6, aR3, aP,  aR,  aR2);
    }

    const int i2 = (IMG - 1) - i, j2 = (IMG - 1) - j;
    // P = (i, j)
    out[i * IMG + j]              = aP.b0;
    out[IMG * IMG + i * IMG + j]  = aP.b1;
    // rP = (j, 511-i)
    out[j * IMG + i2]             = aR.b0;
    out[IMG * IMG + j * IMG + i2] = aR.b1;
    // r2P = (511-i, 511-j)
    out[i2 * IMG + j2]             = aR2.b0;
    out[IMG * IMG + i2 * IMG + j2] = aR2.b1;
    // r3P = (511-j, i)
    out[j2 * IMG + i]             = aR3.b0;
    out[IMG * IMG + j2 * IMG + i] = aR3.b1;
}

// ---------------- entry point ----------------
extern "C" void kernel_launch(void* const* d_in, const int* in_sizes, int n_in,
                              void* d_out, int out_size) {
    (void)in_sizes; (void)n_in; (void)out_size;
    const float* proj = (const float*)d_in[0];   // [2, 360, 768] f32
    float* out = (float*)d_out;                  // [2, 512, 512] f32

    conv_kernel<<<2 * NV, 384>>>(proj);
    pack_kernel<<<NV, NDET>>>();
    bp_kernel<<<dim3(IMG / 2 / 16, IMG / 2 / 4), dim3(16, 4)>>>(out);
}

// round 15
// speedup vs baseline: 1.4198x; 1.2244x over previous
#include <cuda_runtime.h>
#include <cuda_fp16.h>
#include <math.h>

// ---------------- fixed CT geometry ----------------
#define IMG   512
#define NDET  768
#define NV    360
#define GLEN  (2*NDET-1)

#define PIXd  0.7433
#define DSOd  595.0
#define DSDd  1085.6              // 595.0 + 490.6
#define DETd  1.2858
#define DGd   (DETd / DSDd)       // equiangular pitch (rad/bin)
#define INVDGd (DSDd / DETd)
#define SCALEd (DGd * 2.0 * M_PI / 360.0)   // fold q*=DGAMMA and *=2pi/NV

// padded q row: [16 zero | 768 data | 16 zero]; i0 in [-13,779] stays in-row
#define QPAD    16
#define QSTRIDE 800

// half4 = (q0, dq0, q1, dq1), one LDG.64 per (view, detector bin)
struct __align__(8) H4 { __half2 a, b; };

// ---------------- device scratch (no allocations allowed) ----------------
__device__ float2 cs_tab[NV];               // (cos beta, sin beta)
__device__ float2 q_part[2][NV * NDET];     // split-K partial conv results
__device__ H4     q_pack[NV * QSTRIDE];     // fp16-packed, zero-padded
__device__ float  part_img[3][2 * IMG * IMG]; // rot-90/180/270 contributions

// ---------------- conv split-K (R11 proven form, unchanged) ----------------
__global__ void __launch_bounds__(384) conv_kernel(const float* __restrict__ proj) {
    __shared__ float2 p2[384];               // this half's cosine-weighted bins
    __shared__ float  gs[1151];              // this half's ramp taps

    const int v   = blockIdx.x >> 1;
    const int h   = blockIdx.x & 1;
    const int tid = threadIdx.x;
    const int kbase = h * 384;
    const int idx0  = h ? 0 : 384;           // global g-index of gs[0]

    if (h == 0 && tid == 0) {                // per-view angle (double-accurate)
        double sb, cb;
        sincospi((double)v / 180.0, &sb, &cb);
        cs_tab[v] = make_float2((float)cb, (float)sb);
    }
    for (int i = tid; i < 1151; i += 384) {  // ramp taps (fp32: 2e-7 rel)
        int n = (i + idx0) - (NDET - 1);
        float g;
        if (n == 0) {
            g = (float)(SCALEd / (8.0 * DGd * DGd));
        } else if (n & 1) {
            float s = sinf((float)n * (float)DGd) * (float)M_PI;
            g = (float)(-0.5 * SCALEd) / (s * s);
        } else {
            g = 0.0f;
        }
        gs[i] = g;
    }
    {   // cosine-weighted projections for this half's bins
        int bin = kbase + tid;
        float gam = ((float)bin - 383.5f) * (float)DGd;
        float cw  = 595.0f * cosf(gam);
        p2[tid] = make_float2(proj[(0 * NV + v) * NDET + bin] * cw,
                              proj[(1 * NV + v) * NDET + bin] * cw);
    }
    __syncthreads();

    const int t  = tid;                      // output bins t and t+384
    const int t2 = tid + 384;
    const float g0 = (float)(SCALEd / (8.0 * DGd * DGd));

    float a0 = 0.f, a1 = 0.f, b0 = 0.f, b1 = 0.f;
    if (h == 0) { float2 pc = p2[t];         a0 = pc.x * g0; a1 = pc.y * g0; }
    else        { float2 pc = p2[t2 - 384];  b0 = pc.x * g0; b1 = pc.y * g0; }

    const int k0 = (t + 1) & 1;              // parity making (output - k) odd
#pragma unroll 8
    for (int kk = k0; kk < 384; kk += 2) {
        float2 p  = p2[kk];                  // broadcast LDS.64
        float gva = gs[t  - kk + 383];
        float gvb = gs[t2 - kk + 383];
        a0 = fmaf(p.x, gva, a0);
        a1 = fmaf(p.y, gva, a1);
        b0 = fmaf(p.x, gvb, b0);
        b1 = fmaf(p.y, gvb, b1);
    }
    q_part[h][v * NDET + t]  = make_float2(a0, a1);
    q_part[h][v * NDET + t2] = make_float2(b0, b1);
}

// ---------------- pack: sum halves + pre-diff + fp16 pack + pads -----------
__global__ void __launch_bounds__(NDET) pack_kernel() {
    __shared__ float2 qs[NDET];
    const int v = blockIdx.x;
    const int t = threadIdx.x;

    float2 qa0 = q_part[0][v * NDET + t];
    float2 qa1 = q_part[1][v * NDET + t];
    qs[t] = make_float2(qa0.x + qa1.x, qa0.y + qa1.y);   // fixed order: determ.
    if (t < QPAD) {
        H4 z; z.a = __floats2half2_rn(0.f, 0.f); z.b = z.a;
        q_pack[v * QSTRIDE + t]               = z;
        q_pack[v * QSTRIDE + QPAD + NDET + t] = z;
    }
    __syncthreads();

    float2 qa = qs[t];
    float2 qb = qs[min(t + 1, NDET - 1)];
    H4 o;
    o.a = __floats2half2_rn(qa.x, qb.x - qa.x);          // (q0, dq0)
    o.b = __floats2half2_rn(qa.y, qb.y - qa.y);          // (q1, dq1)
    q_pack[v * QSTRIDE + QPAD + t] = o;
}

// ---------------- backprojection with 4-fold rotation symmetry -------------
// R11 proven structure; q rows now fp16 half4 -> LDG.64 (half the L1
// wavefronts of the float4 version; bp is L1-wavefront bound).
__global__ void __launch_bounds__(128, 12) bp_kernel(float* __restrict__ out) {
    __shared__ float2 cs_s[NV / 4];
    const int tid = threadIdx.y * 16 + threadIdx.x;
    if (tid < NV / 4) cs_s[tid] = cs_tab[tid];
    __syncthreads();

    const int j = (blockIdx.x << 4) + threadIdx.x;
    const int i = (blockIdx.y << 3) + threadIdx.y;

    const float x = ((float)j - 255.5f) * (float)PIXd;
    const float y = ((float)i - 255.5f) * (float)PIXd;
    const float DSOf = 595.0f;

    // asin Taylor coefficients * (1/DGAMMA), degree 13
    const float A0 = (float)(INVDGd);
    const float A1 = (float)(INVDGd / 6.0);
    const float A2 = (float)(INVDGd * 0.075);
    const float A3 = (float)(INVDGd * 0.044642857);
    const float A4 = (float)(INVDGd * 0.030381944);
    const float A5 = (float)(INVDGd * 0.022372159);
    const float A6 = (float)(INVDGd * 0.017352764);

    float aS0 = 0.f, aS1 = 0.f;              // self pixel,     views 0..89
    float a90_0 = 0.f, a90_1 = 0.f;          // rot +90 pixel,  views 90..179
    float a180_0 = 0.f, a180_1 = 0.f;        // rot 180 pixel,  views 180..269
    float a270_0 = 0.f, a270_1 = 0.f;        // rot 270 pixel,  views 270..359

    const H4* __restrict__ qp = q_pack + QPAD;

#pragma unroll 3
    for (int v = 0; v < NV / 4; ++v) {
        float2 cs = cs_s[v];
        float u  = fmaf(cs.x, x,  cs.y * y);
        float cr = fmaf(cs.y, x, -cs.x * y);
        float dt = DSOf - u;
        float L2 = fmaf(dt, dt, cr * cr);
        float rsq;
        asm("rsqrt.approx.f32 %0, %1;" : "=f"(rsq) : "f"(L2));
        float s  = cr * rsq;                 // sin(theta), dt > 0 always
        float s2 = s * s;
        float p  = fmaf(A6, s2, A5);
        p = fmaf(p, s2, A4);
        p = fmaf(p, s2, A3);
        p = fmaf(p, s2, A2);
        p = fmaf(p, s2, A1);
        p = fmaf(p, s2, A0);
        float tv = s * p;                    // g - 383.5 (detector offset)
        float g  = tv + 383.5f;

        float T  = (g - 0.5f) + 12582912.0f; // round(g-0.5) == floor(g)
        int   i0 = __float_as_int(T) - 0x4B400000;
        float fg = T - 12582912.0f;
        float w_ = g - fg;
        float m  = rsq * rsq;                // 1/L2
        float wl = (fabsf(tv) <= 383.5f) ? m : 0.0f;   // g in [0,767]

        const H4* qv = qp + v * QSTRIDE + i0;
        H4 qa = qv[0];                              // view v
        H4 qb = qv[ 90 * QSTRIDE];                  // view v+90
        H4 qc = qv[180 * QSTRIDE];                  // view v+180
        H4 qd = qv[270 * QSTRIDE];                  // view v+270
        float2 a0 = __half22float2(qa.a), a1 = __half22float2(qa.b);
        float2 b0 = __half22float2(qb.a), b1 = __half22float2(qb.b);
        float2 c0 = __half22float2(qc.a), c1 = __half22float2(qc.b);
        float2 d0 = __half22float2(qd.a), d1 = __half22float2(qd.b);
        aS0    = fmaf(fmaf(w_, a0.y, a0.x), wl, aS0);
        aS1    = fmaf(fmaf(w_, a1.y, a1.x), wl, aS1);
        a90_0  = fmaf(fmaf(w_, b0.y, b0.x), wl, a90_0);
        a90_1  = fmaf(fmaf(w_, b1.y, b1.x), wl, a90_1);
        a180_0 = fmaf(fmaf(w_, c0.y, c0.x), wl, a180_0);
        a180_1 = fmaf(fmaf(w_, c1.y, c1.x), wl, a180_1);
        a270_0 = fmaf(fmaf(w_, d0.y, d0.x), wl, a270_0);
        a270_1 = fmaf(fmaf(w_, d1.y, d1.x), wl, a270_1);
    }

    out[i * IMG + j]             = aS0;
    out[IMG * IMG + i * IMG + j] = aS1;
    // rot +90: pixel (i', j') = (j, 511-i)
    part_img[0][j * IMG + (IMG - 1 - i)]             = a90_0;
    part_img[0][IMG * IMG + j * IMG + (IMG - 1 - i)] = a90_1;
    // rot 180: (511-i, 511-j)
    part_img[1][(IMG - 1 - i) * IMG + (IMG - 1 - j)]             = a180_0;
    part_img[1][IMG * IMG + (IMG - 1 - i) * IMG + (IMG - 1 - j)] = a180_1;
    // rot 270: (511-j, i)
    part_img[2][(IMG - 1 - j) * IMG + i]             = a270_0;
    part_img[2][IMG * IMG + (IMG - 1 - j) * IMG + i] = a270_1;
}

// ---------------- combine: out += s90 + s180 + s270 ------------------------
__global__ void __launch_bounds__(512) combine_kernel(float* __restrict__ out) {
    int t = blockIdx.x * 512 + threadIdx.x;          // float4 index
    float4* o = (float4*)out;
    const float4* p0 = (const float4*)part_img[0];
    const float4* p1 = (const float4*)part_img[1];
    const float4* p2 = (const float4*)part_img[2];
    float4 a = o[t], b = p0[t], c = p1[t], d = p2[t];
    o[t] = make_float4(a.x + b.x + c.x + d.x,
                       a.y + b.y + c.y + d.y,
                       a.z + b.z + c.z + d.z,
                       a.w + b.w + c.w + d.w);
}

// ---------------- entry point ----------------
extern "C" void kernel_launch(void* const* d_in, const int* in_sizes, int n_in,
                              void* d_out, int out_size) {
    (void)in_sizes; (void)n_in; (void)out_size;
    const float* proj = (const float*)d_in[0];   // [2, 360, 768] f32
    float* out = (float*)d_out;                  // [2, 512, 512] f32

    conv_kernel<<<2 * NV, 384>>>(proj);
    pack_kernel<<<NV, NDET>>>();
    bp_kernel<<<dim3(IMG / 16, IMG / 8), dim3(16, 8)>>>(out);
    combine_kernel<<<(2 * IMG * IMG / 4) / 512, 512>>>(out);
}

// round 16
// speedup vs baseline: 1.7529x; 1.2346x over previous
#include <cuda_runtime.h>
#include <cuda_fp16.h>
#include <math.h>

// ---------------- fixed CT geometry ----------------
#define IMG   512
#define NDET  768
#define NV    360

#define PIXd  0.7433
#define DSOd  595.0
#define DSDd  1085.6              // 595.0 + 490.6
#define DETd  1.2858
#define DGd   (DETd / DSDd)       // equiangular pitch (rad/bin)
#define INVDGd (DSDd / DETd)
#define SCALEd (DGd * 2.0 * M_PI / 360.0)   // fold q*=DGAMMA and *=2pi/NV

// padded q row: [16 zero | 768 data | 16 zero]; i0 in [-13,779] stays in-row
#define QPAD    16
#define QSTRIDE 800

// half4: a = (q0, q1), b = (dq0, dq1)  -> one HFMA2 interpolates both batches
struct __align__(8) H4 { __half2 a, b; };

// ---------------- device scratch (no allocations allowed) ----------------
__device__ float2 cs_tab[NV];               // (cos beta, sin beta)
__device__ float2 q_part[4][NV * NDET];     // split-K quarter partials
__device__ H4     q_pack[NV * QSTRIDE];     // fp16-packed, zero-padded
__device__ float  part_img[3][2 * IMG * IMG]; // rot-90/180/270 contributions

// ---------------- conv: block = (view pair, K quarter) ---------------------
// 2 views share each gs load: 4 LDS wavefronts serve 8 FMAs per iteration.
// Quarter Q covers taps k in [192Q, 192Q+192). Outputs t=tid and t2=t+384.
// gsl[li] = g(li - 191 - 192Q), li = t - kk + 191 (t path), t2 path +384.
__global__ void __launch_bounds__(384) conv_kernel(const float* __restrict__ proj) {
    __shared__ float2 p2[2][192];            // [view][local tap], (batch0,batch1)
    __shared__ float  gsl[959];              // this quarter's ramp taps

    const int pair = blockIdx.x >> 2;
    const int Q    = blockIdx.x & 3;
    const int v0   = 2 * pair;
    const int tid  = threadIdx.x;

    if (Q == 0 && tid < 2) {                 // per-view angles (double-accurate)
        double sb, cb;
        sincospi((double)(v0 + tid) / 180.0, &sb, &cb);
        cs_tab[v0 + tid] = make_float2((float)cb, (float)sb);
    }
    for (int i = tid; i < 959; i += 384) {   // ramp taps (fp32: 2e-7 rel)
        int n = i - 191 - 192 * Q;
        float g;
        if (n == 0) {
            g = (float)(SCALEd / (8.0 * DGd * DGd));
        } else if (n & 1) {
            float s = sinf((float)n * (float)DGd) * (float)M_PI;
            g = (float)(-0.5 * SCALEd) / (s * s);
        } else {
            g = 0.0f;
        }
        gsl[i] = g;
    }
    {   // cosine-weighted projections: 2 views x 192 bins, one per thread
        int view = tid / 192;                // 0 or 1
        int kk   = tid % 192;
        int bin  = 192 * Q + kk;
        int v    = v0 + view;
        float gam = ((float)bin - 383.5f) * (float)DGd;
        float cw  = 595.0f * cosf(gam);
        p2[view][kk] = make_float2(proj[(0 * NV + v) * NDET + bin] * cw,
                                   proj[(1 * NV + v) * NDET + bin] * cw);
    }
    __syncthreads();

    const int t  = tid;                      // outputs t and t+384
    const int t2 = tid + 384;
    const float g0 = (float)(SCALEd / (8.0 * DGd * DGd));

    float a0 = 0.f, a1 = 0.f, a2 = 0.f, a3 = 0.f;   // view v0: (t b0,b1), (t2 b0,b1)
    float b0 = 0.f, b1 = 0.f, b2 = 0.f, b3 = 0.f;   // view v0+1

    // center tap (n = 0, even) excluded from parity loop; add if k=t (or t2)
    // falls in this quarter
    if (t >= 192 * Q && t < 192 * Q + 192) {
        float2 pa = p2[0][t - 192 * Q], pb = p2[1][t - 192 * Q];
        a0 = pa.x * g0; a1 = pa.y * g0;
        b0 = pb.x * g0; b1 = pb.y * g0;
    }
    if (t2 >= 192 * Q && t2 < 192 * Q + 192) {
        float2 pa = p2[0][t2 - 192 * Q], pb = p2[1][t2 - 192 * Q];
        a2 = pa.x * g0; a3 = pa.y * g0;
        b2 = pb.x * g0; b3 = pb.y * g0;
    }

    const int k0 = (t + 1) & 1;              // local parity making (t-k) odd
#pragma unroll 8
    for (int kk = k0; kk < 192; kk += 2) {
        float2 pa = p2[0][kk];               // broadcast LDS.64
        float2 pb = p2[1][kk];               // broadcast LDS.64
        float gva = gsl[t  - kk + 191];      // stride-1
        float gvb = gsl[t2 - kk + 191];      // stride-1 (offset +384)
        a0 = fmaf(pa.x, gva, a0);
        a1 = fmaf(pa.y, gva, a1);
        a2 = fmaf(pa.x, gvb, a2);
        a3 = fmaf(pa.y, gvb, a3);
        b0 = fmaf(pb.x, gva, b0);
        b1 = fmaf(pb.y, gva, b1);
        b2 = fmaf(pb.x, gvb, b2);
        b3 = fmaf(pb.y, gvb, b3);
    }
    q_part[Q][ v0      * NDET + t ] = make_float2(a0, a1);
    q_part[Q][ v0      * NDET + t2] = make_float2(a2, a3);
    q_part[Q][(v0 + 1) * NDET + t ] = make_float2(b0, b1);
    q_part[Q][(v0 + 1) * NDET + t2] = make_float2(b2, b3);
}

// ---------------- pack: sum quarters + pre-diff + fp16 pack + pads ---------
__global__ void __launch_bounds__(NDET) pack_kernel() {
    __shared__ float2 qs[NDET];
    const int v = blockIdx.x;
    const int t = threadIdx.x;

    float2 p0 = q_part[0][v * NDET + t];
    float2 p1 = q_part[1][v * NDET + t];
    float2 p2 = q_part[2][v * NDET + t];
    float2 p3 = q_part[3][v * NDET + t];
    qs[t] = make_float2((p0.x + p1.x) + (p2.x + p3.x),   // fixed order: determ.
                        (p0.y + p1.y) + (p2.y + p3.y));
    if (t < QPAD) {
        H4 z; z.a = __floats2half2_rn(0.f, 0.f); z.b = z.a;
        q_pack[v * QSTRIDE + t]               = z;
        q_pack[v * QSTRIDE + QPAD + NDET + t] = z;
    }
    __syncthreads();

    float2 qa = qs[t];
    float2 qb = qs[min(t + 1, NDET - 1)];
    H4 o;
    o.a = __floats2half2_rn(qa.x, qa.y);                 // (q0, q1)
    o.b = __floats2half2_rn(qb.x - qa.x, qb.y - qa.y);   // (dq0, dq1)
    q_pack[v * QSTRIDE + QPAD + t] = o;
}

// ---------------- backprojection with 4-fold rotation symmetry -------------
// fp16 q rows (LDG.64), HFMA2 interpolation: one hfma2 serves both batches.
__global__ void __launch_bounds__(128, 12) bp_kernel(float* __restrict__ out) {
    __shared__ float2 cs_s[NV / 4];
    const int tid = threadIdx.y * 16 + threadIdx.x;
    if (tid < NV / 4) cs_s[tid] = cs_tab[tid];
    __syncthreads();

    const int j = (blockIdx.x << 4) + threadIdx.x;
    const int i = (blockIdx.y << 3) + threadIdx.y;

    const float x = ((float)j - 255.5f) * (float)PIXd;
    const float y = ((float)i - 255.5f) * (float)PIXd;
    const float DSOf = 595.0f;

    // asin Taylor coefficients * (1/DGAMMA), degree 13
    const float A0 = (float)(INVDGd);
    const float A1 = (float)(INVDGd / 6.0);
    const float A2 = (float)(INVDGd * 0.075);
    const float A3 = (float)(INVDGd * 0.044642857);
    const float A4 = (float)(INVDGd * 0.030381944);
    const float A5 = (float)(INVDGd * 0.022372159);
    const float A6 = (float)(INVDGd * 0.017352764);

    float aS0 = 0.f, aS1 = 0.f;              // self pixel,     views 0..89
    float a90_0 = 0.f, a90_1 = 0.f;          // rot +90 pixel,  views 90..179
    float a180_0 = 0.f, a180_1 = 0.f;        // rot 180 pixel,  views 180..269
    float a270_0 = 0.f, a270_1 = 0.f;        // rot 270 pixel,  views 270..359

    const H4* __restrict__ qp = q_pack + QPAD;

#pragma unroll 3
    for (int v = 0; v < NV / 4; ++v) {
        float2 cs = cs_s[v];
        float u  = fmaf(cs.x, x,  cs.y * y);
        float cr = fmaf(cs.y, x, -cs.x * y);
        float dt = DSOf - u;
        float L2 = fmaf(dt, dt, cr * cr);
        float rsq;
        asm("rsqrt.approx.f32 %0, %1;" : "=f"(rsq) : "f"(L2));
        float s  = cr * rsq;                 // sin(theta), dt > 0 always
        float s2 = s * s;
        float p  = fmaf(A6, s2, A5);
        p = fmaf(p, s2, A4);
        p = fmaf(p, s2, A3);
        p = fmaf(p, s2, A2);
        p = fmaf(p, s2, A1);
        p = fmaf(p, s2, A0);
        float tv = s * p;                    // g - 383.5 (detector offset)
        float g  = tv + 383.5f;

        float T  = (g - 0.5f) + 12582912.0f; // round(g-0.5) == floor(g)
        int   i0 = __float_as_int(T) - 0x4B400000;
        float fg = T - 12582912.0f;
        float w_ = g - fg;
        float m  = rsq * rsq;                // 1/L2
        float wl = (fabsf(tv) <= 383.5f) ? m : 0.0f;   // g in [0,767]
        __half2 w2 = __float2half2_rn(w_);

        const H4* qv = qp + v * QSTRIDE + i0;
        H4 qa = qv[0];                              // view v
        H4 qb = qv[ 90 * QSTRIDE];                  // view v+90
        H4 qc = qv[180 * QSTRIDE];                  // view v+180
        H4 qd = qv[270 * QSTRIDE];                  // view v+270
        float2 fa = __half22float2(__hfma2(w2, qa.b, qa.a));
        float2 fb = __half22float2(__hfma2(w2, qb.b, qb.a));
        float2 fc = __half22float2(__hfma2(w2, qc.b, qc.a));
        float2 fd = __half22float2(__hfma2(w2, qd.b, qd.a));
        aS0    = fmaf(fa.x, wl, aS0);
        aS1    = fmaf(fa.y, wl, aS1);
        a90_0  = fmaf(fb.x, wl, a90_0);
        a90_1  = fmaf(fb.y, wl, a90_1);
        a180_0 = fmaf(fc.x, wl, a180_0);
        a180_1 = fmaf(fc.y, wl, a180_1);
        a270_0 = fmaf(fd.x, wl, a270_0);
        a270_1 = fmaf(fd.y, wl, a270_1);
    }

    out[i * IMG + j]             = aS0;
    out[IMG * IMG + i * IMG + j] = aS1;
    // rot +90: pixel (i', j') = (j, 511-i)
    part_img[0][j * IMG + (IMG - 1 - i)]             = a90_0;
    part_img[0][IMG * IMG + j * IMG + (IMG - 1 - i)] = a90_1;
    // rot 180: (511-i, 511-j)
    part_img[1][(IMG - 1 - i) * IMG + (IMG - 1 - j)]             = a180_0;
    part_img[1][IMG * IMG + (IMG - 1 - i) * IMG + (IMG - 1 - j)] = a180_1;
    // rot 270: (511-j, i)
    part_img[2][(IMG - 1 - j) * IMG + i]             = a270_0;
    part_img[2][IMG * IMG + (IMG - 1 - j) * IMG + i] = a270_1;
}

// ---------------- combine: out += s90 + s180 + s270 ------------------------
__global__ void __launch_bounds__(256) combine_kernel(float* __restrict__ out) {
    int t = blockIdx.x * 256 + threadIdx.x;          // float4 index
    float4* o = (float4*)out;
    const float4* p0 = (const float4*)part_img[0];
    const float4* p1 = (const float4*)part_img[1];
    const float4* p2 = (const float4*)part_img[2];
    float4 a = o[t], b = p0[t], c = p1[t], d = p2[t];
    o[t] = make_float4(a.x + b.x + c.x + d.x,
                       a.y + b.y + c.y + d.y,
                       a.z + b.z + c.z + d.z,
                       a.w + b.w + c.w + d.w);
}

// ---------------- entry point ----------------
extern "C" void kernel_launch(void* const* d_in, const int* in_sizes, int n_in,
                              void* d_out, int out_size) {
    (void)in_sizes; (void)n_in; (void)out_size;
    const float* proj = (const float*)d_in[0];   // [2, 360, 768] f32
    float* out = (float*)d_out;                  // [2, 512, 512] f32

    conv_kernel<<<4 * (NV / 2), 384>>>(proj);
    pack_kernel<<<NV, NDET>>>();
    bp_kernel<<<dim3(IMG / 16, IMG / 8), dim3(16, 8)>>>(out);
    combine_kernel<<<(2 * IMG * IMG / 4) / 256, 256>>>(out);
}